// round 5
// baseline (speedup 1.0000x reference)
#include <cuda_runtime.h>

#define TPB   512
#define CAP   4096
#define NBH   8192          // coarse histogram buckets (13 bits)
#define NSEG  (NBH / TPB)   // 16 buckets per thread segment
#define TOPN  2048
#define EPSF  1e-9f

__device__ __forceinline__ float key_p(unsigned long long k) {
    return __uint_as_float((unsigned int)(k >> 32));
}

// Pinned-arithmetic p computation: MUST be bitwise identical in every pass.
__device__ __forceinline__ unsigned int pbits_of(float l, float temp, float m, float Z) {
    float y = __fdiv_rn(l, temp);
    float d = __fsub_rn(y, m);
    float e = expf(d);
    float p = __fdiv_rn(e, Z);
    return __float_as_uint(p);
}

// Monotone unsigned mapping of float bits (no NaNs in inputs).
__device__ __forceinline__ unsigned int fkey(unsigned int b) {
    return (b & 0x80000000u) ? ~b : (b | 0x80000000u);
}

// Warp-aggregated histogram add: one atomic per distinct bucket per warp.
__device__ __forceinline__ void hist_add(unsigned int* hist, unsigned bkt) {
    unsigned act = __activemask();
    unsigned mask = __match_any_sync(act, bkt);
    int leader = __ffs(mask) - 1;
    if ((int)(threadIdx.x & 31) == leader)
        atomicAdd(&hist[bkt], (unsigned)__popc(mask));
}

__global__ __launch_bounds__(TPB, 2)
void sampler_kernel(const float* __restrict__ logits,
                    const float* __restrict__ temps,
                    const int*   __restrict__ topks,
                    const float* __restrict__ topps,
                    const float* __restrict__ minps,
                    const int*   __restrict__ poss,
                    const int*   __restrict__ seeds,
                    float* __restrict__ out_ids,
                    float* __restrict__ out_lp,
                    int V, int write_lp)
{
    __shared__ unsigned long long cand[CAP];   // 32 KB; aliases hist (8192 u32)
    __shared__ float scanA[TOPN];              // 8 KB; aliases redF/redS/partS
    __shared__ int   redI[TPB];                // 2 KB
    __shared__ float sh_m, sh_Z, sh_logZ;
    __shared__ unsigned int sh_thresh, sh_cnt, sh_above;
    __shared__ int sh_b, sh_refine, sh_Kcut, sh_jwin, sh_token;

    unsigned int* hist  = (unsigned int*)cand;           // 8192 buckets
    float*        redF  = scanA;                         // [0..512)
    float*        redS  = scanA + TPB;                   // [512..1024)
    unsigned int* partS = (unsigned int*)(scanA + 2*TPB);// [1024..1536)

    const int row = blockIdx.x;
    const int tid = threadIdx.x;
    const float temp = temps[row];
    const float* lrow = logits + (size_t)row * V;
    float* lprow = out_lp + (size_t)row * V;

    // zero coarse histogram
    #pragma unroll
    for (int k2 = 0; k2 < NSEG; k2++) hist[tid + k2 * TPB] = 0;
    __syncthreads();

    // ---------- Pass A: online max + sum of exp (IDENTICAL arithmetic to R2)
    //            + logit-bit histogram (ALU only, warp-aggregated) ----------
    float m = -3.402823466e38f;
    float s = 0.0f;
    for (int j = tid * 4; j < V; j += TPB * 4) {
        float4 v = *reinterpret_cast<const float4*>(lrow + j);
        float ys[4];
        ys[0] = __fdiv_rn(v.x, temp); ys[1] = __fdiv_rn(v.y, temp);
        ys[2] = __fdiv_rn(v.z, temp); ys[3] = __fdiv_rn(v.w, temp);
        #pragma unroll
        for (int q = 0; q < 4; q++) {
            float y = ys[q];
            if (y > m) { s *= expf(m - y); m = y; }
            s += expf(y - m);
        }
        float ls[4] = {v.x, v.y, v.z, v.w};
        #pragma unroll
        for (int q = 0; q < 4; q++)
            hist_add(hist, fkey(__float_as_uint(ls[q])) >> 19);
    }
    redF[tid] = m; redS[tid] = s;
    __syncthreads();
    for (int off = TPB / 2; off > 0; off >>= 1) {
        if (tid < off) {
            float m2 = redF[tid + off], s2 = redS[tid + off];
            float M = fmaxf(redF[tid], m2);
            redS[tid] = redS[tid] * expf(redF[tid] - M) + s2 * expf(m2 - M);
            redF[tid] = M;
        }
        __syncthreads();
    }
    if (tid == 0) { sh_m = redF[0]; sh_Z = redS[0]; sh_logZ = logf(redS[0]); }
    __syncthreads();
    m = sh_m;
    const float Z = sh_Z;
    const float logZ = sh_logZ;

    // ---------- parallel threshold selection (suffix scan over segments) ----------
    {
        unsigned lsum = 0;
        #pragma unroll
        for (int k2 = 0; k2 < NSEG; k2++) lsum += hist[tid * NSEG + k2];
        partS[tid] = lsum;
        __syncthreads();
        for (int off = 1; off < TPB; off <<= 1) {
            unsigned add = (tid + off < TPB) ? partS[tid + off] : 0u;
            __syncthreads();
            partS[tid] += add;
            __syncthreads();
        }
        // partS[t] = count of elements in buckets >= 16*t (non-increasing)
        if (partS[tid] >= TOPN && (tid == TPB - 1 || partS[tid + 1] < TOPN)) {
            unsigned A = (tid == TPB - 1) ? 0u : partS[tid + 1];
            int b = tid * NSEG + NSEG - 1;
            for (; b >= tid * NSEG; --b) { A += hist[b]; if (A >= TOPN) break; }
            sh_b = b;
            sh_above = A - hist[b];
            sh_refine = (A > CAP) ? 1 : 0;
            sh_thresh = ((unsigned)b) << 19;
        }
        __syncthreads();
    }

    // ---------- rare refine pass (cut bucket too big) ----------
    if (sh_refine) {
        #pragma unroll
        for (int k2 = 0; k2 < NSEG; k2++) hist[tid + k2 * TPB] = 0;
        __syncthreads();
        int b = sh_b;
        for (int j = tid * 4; j < V; j += TPB * 4) {
            float4 v = *reinterpret_cast<const float4*>(lrow + j);
            float ls[4] = {v.x, v.y, v.z, v.w};
            #pragma unroll
            for (int q = 0; q < 4; q++) {
                unsigned k = fkey(__float_as_uint(ls[q]));
                if ((int)(k >> 19) == b) atomicAdd(&hist[(k >> 6) & (NBH - 1)], 1u);
            }
        }
        __syncthreads();
        if (tid == 0) {
            unsigned cum = sh_above; int sb = NBH - 1;
            for (; sb >= 0; --sb) {
                unsigned c = hist[sb];
                if (cum + c >= TOPN) break;
                cum += c;
            }
            if (sb < 0) sb = 0;
            sh_thresh = (((unsigned)sh_b) << 19) | (((unsigned)sb) << 6);
        }
        __syncthreads();
    }

    // ---------- Pass B: logprobs out + fused candidate gather (no expf/elem) ----------
    if (tid == 0) sh_cnt = 0;
    __syncthreads();
    {
        const unsigned th = sh_thresh;
        for (int j = tid * 8; j < V; j += TPB * 8) {
            float4 a = *reinterpret_cast<const float4*>(lrow + j);
            float4 b4 = *reinterpret_cast<const float4*>(lrow + j + 4);
            float ls[8] = {a.x, a.y, a.z, a.w, b4.x, b4.y, b4.z, b4.w};
            float o[8];
            #pragma unroll
            for (int q = 0; q < 8; q++) {
                float y = __fdiv_rn(ls[q], temp);
                float d = __fsub_rn(y, m);
                o[q] = d - logZ;
                unsigned k = fkey(__float_as_uint(ls[q]));
                if (k >= th) {
                    unsigned pos = atomicAdd(&sh_cnt, 1u);
                    if (pos < CAP) {
                        unsigned pb = pbits_of(ls[q], temp, m, Z);
                        cand[pos] = ((unsigned long long)pb << 32) | (unsigned)(j + q);
                    }
                }
            }
            if (write_lp) {
                *reinterpret_cast<float4*>(lprow + j)     = make_float4(o[0], o[1], o[2], o[3]);
                *reinterpret_cast<float4*>(lprow + j + 4) = make_float4(o[4], o[5], o[6], o[7]);
            }
        }
    }
    __syncthreads();
    {
        int n = (int)min(sh_cnt, (unsigned)CAP);
        for (int i = tid; i < CAP; i += TPB)
            if (i >= n) cand[i] = 0ULL;
    }
    __syncthreads();

    // ---------- bitonic sort (descending by 64-bit (pbits,idx) key) ----------
    for (int k = 2; k <= CAP; k <<= 1) {
        for (int jj = k >> 1; jj > 0; jj >>= 1) {
            for (int i = tid; i < CAP; i += TPB) {
                int l = i ^ jj;
                if (l > i) {
                    unsigned long long a = cand[i], b2 = cand[l];
                    bool descBlock = ((i & k) == 0);
                    bool doswap = descBlock ? (a < b2) : (a > b2);
                    if (doswap) { cand[i] = b2; cand[l] = a; }
                }
            }
            __syncthreads();
        }
    }

    // ---------- inclusive scan over top-TOPN probs ----------
    float* src = scanA;                       // 2048 floats
    float* dst = (float*)(cand + TOPN);       // reuse upper cand space
    for (int i = tid; i < TOPN; i += TPB) src[i] = key_p(cand[i]);
    __syncthreads();
    for (int off = 1; off < TOPN; off <<= 1) {
        for (int i = tid; i < TOPN; i += TPB) {
            float x = src[i];
            if (i >= off) x += src[i - off];
            dst[i] = x;
        }
        __syncthreads();
        float* t = src; src = dst; dst = t;
    }

    // ---------- K_cut: first violated position ----------
    {
        int tk = topks[row]; if (tk > TOPN) tk = TOPN;
        float tp = topps[row];
        float mp = minps[row];
        float p0 = key_p(cand[0]);
        float thr = p0 * mp;
        int kl = tk;
        for (int i = tid; i < tk; i += TPB) {
            float pi = key_p(cand[i]);
            if ((src[i] - pi) > tp || pi < thr) kl = min(kl, i);
        }
        redI[tid] = kl;
        __syncthreads();
        for (int off = TPB / 2; off > 0; off >>= 1) {
            if (tid < off) redI[tid] = min(redI[tid], redI[tid + off]);
            __syncthreads();
        }
        if (tid == 0) sh_Kcut = redI[0];
        __syncthreads();
    }
    const int Kcut = sh_Kcut;

    // ---------- gumbel argmax: head (exact vals) + tail (integer hash max) ----------
    {
        unsigned ss = (unsigned)seeds[row] * 19349663u ^ (unsigned)poss[row] * 73856093u;
        const float CZ = logf(EPSF);

        // head: ranks [0, Kcut)
        float bv = -3.402823466e38f; int bj = 0x7FFFFFFF;
        for (int j = tid; j < Kcut; j += TPB) {
            unsigned h = ss * 805306457u ^ (unsigned)j * 479001599u;
            float u = (float)(h & 0xFFFFFFu) * (1.0f / 16777216.0f);
            float g = -logf(-logf(u + EPSF) + EPSF);
            float val = logf(key_p(cand[j]) + EPSF) + g;
            if (val > bv) { bv = val; bj = j; }   // ascending j per thread
        }

        // tail: ranks [Kcut, V) — val = CZ + g(u) monotone in u24;
        // exact val tie only for bit-equal u → smallest rank wins.
        unsigned long long bestT = 0ULL;          // (u24 << 24) | (V - j)
        for (int j = Kcut + tid; j < V; j += TPB) {
            unsigned h = ss * 805306457u ^ (unsigned)j * 479001599u;
            unsigned u = h & 0xFFFFFFu;
            unsigned long long pk = ((unsigned long long)u << 24) | (unsigned)(V - j);
            if (pk > bestT) bestT = pk;
        }

        redF[tid] = bv; redI[tid] = bj;
        unsigned long long* tred = cand + 2048 + 1024;  // free region (scan buffers done)
        tred[tid] = bestT;
        __syncthreads();
        for (int off = TPB / 2; off > 0; off >>= 1) {
            if (tid < off) {
                float v2 = redF[tid + off]; int j2 = redI[tid + off];
                if (v2 > redF[tid] || (v2 == redF[tid] && j2 < redI[tid])) {
                    redF[tid] = v2; redI[tid] = j2;
                }
                unsigned long long t2 = tred[tid + off];
                if (t2 > tred[tid]) tred[tid] = t2;
            }
            __syncthreads();
        }
        if (tid == 0) {
            float bvH = redF[0]; int bjH = redI[0];
            unsigned long long bt = tred[0];
            unsigned uT = (unsigned)(bt >> 24);
            int jT = V - (int)(bt & 0xFFFFFFu);
            float u = (float)uT * (1.0f / 16777216.0f);
            float g = -logf(-logf(u + EPSF) + EPSF);
            float valT = CZ + g;
            int token, jwin = -1;
            if (bvH >= valT) {                 // tie -> head (smaller rank)
                token = (int)(unsigned)(cand[bjH] & 0xFFFFFFFFULL);
            } else if (jT < TOPN) {
                token = (int)(unsigned)(cand[jT] & 0xFFFFFFFFULL);
            } else {
                token = -1; jwin = jT;         // rare exact fallback
            }
            sh_token = token; sh_jwin = jwin;
        }
        __syncthreads();
    }

    // ---------- rare exact fallback: winner rank >= TOPN ----------
    if (sh_token < 0) {
        int jw = sh_jwin;
        auto blockCountGE = [&](unsigned t) -> int {
            int c = 0;
            for (int j = tid * 4; j < V; j += TPB * 4) {
                float4 v = *reinterpret_cast<const float4*>(lrow + j);
                float ls[4] = {v.x, v.y, v.z, v.w};
                #pragma unroll
                for (int q = 0; q < 4; q++)
                    c += (pbits_of(ls[q], temp, m, Z) >= t) ? 1 : 0;
            }
            redI[tid] = c; __syncthreads();
            for (int off = TPB / 2; off > 0; off >>= 1) {
                if (tid < off) redI[tid] += redI[tid + off];
                __syncthreads();
            }
            int tot = redI[0]; __syncthreads();
            return tot;
        };
        unsigned lo = 0, hi = 0x7F800000u;
        while (lo < hi) {
            unsigned mid = lo + (hi - lo + 1u) / 2u;
            if (blockCountGE(mid) >= jw + 1) lo = mid; else hi = mid - 1u;
        }
        unsigned P = lo;
        int cgt = blockCountGE(P + 1u);
        int r = jw - cgt;   // rank among equal-p elements (idx descending)
        auto blockCountEqGe = [&](unsigned Pv, int vidx) -> int {
            int c = 0;
            for (int j = tid * 4; j < V; j += TPB * 4) {
                float4 v = *reinterpret_cast<const float4*>(lrow + j);
                float ls[4] = {v.x, v.y, v.z, v.w};
                #pragma unroll
                for (int q = 0; q < 4; q++)
                    c += (pbits_of(ls[q], temp, m, Z) == Pv && (j + q) >= vidx) ? 1 : 0;
            }
            redI[tid] = c; __syncthreads();
            for (int off = TPB / 2; off > 0; off >>= 1) {
                if (tid < off) redI[tid] += redI[tid + off];
                __syncthreads();
            }
            int tot = redI[0]; __syncthreads();
            return tot;
        };
        int l2 = 0, h2 = V - 1;
        while (l2 < h2) {
            int midv = l2 + (h2 - l2 + 1) / 2;
            if (blockCountEqGe(P, midv) >= r + 1) l2 = midv; else h2 = midv - 1;
        }
        if (tid == 0) sh_token = l2;
        __syncthreads();
    }

    if (tid == 0 && out_ids) out_ids[row] = (float)sh_token;
}

extern "C" void kernel_launch(void* const* d_in, const int* in_sizes, int n_in,
                              void* d_out, int out_size) {
    const float* logits = (const float*)d_in[0];
    const float* temps  = (const float*)d_in[1];
    const int*   topks  = (const int*)d_in[2];
    const float* topps  = (const float*)d_in[3];
    const float* minps  = (const float*)d_in[4];
    const int*   poss   = (const int*)d_in[5];
    const int*   seeds  = (const int*)d_in[6];

    int B = in_sizes[1];              // temperatures: [B,1]
    int V = in_sizes[0] / B;          // logits: [B,V]
    long long BV = (long long)B * (long long)V;

    float* out = (float*)d_out;
    float* out_ids = nullptr;
    float* out_lp = nullptr;
    int write_lp = 0;

    if ((long long)out_size >= BV + B) {           // [ids(B), logprobs(B*V)]
        out_ids = out; out_lp = out + B; write_lp = 1;
    } else if ((long long)out_size >= BV) {        // logprobs only
        out_lp = out; write_lp = 1;
    } else {                                        // ids only
        out_ids = out; out_lp = out; write_lp = 0;
    }

    sampler_kernel<<<B, TPB>>>(logits, temps, topks, topps, minps, poss, seeds,
                               out_ids, out_lp, V, write_lp);
}